// round 2
// baseline (speedup 1.0000x reference)
#include <cuda_runtime.h>
#include <cuda_bf16.h>

#define N_NODES 50000
#define TOPK    32
#define IN_C    128
#define OUT_C   64
#define NEG_SLOPE 0.2f
#define BN_EPS  1e-5f

// ---------------- scratch (static device globals; no allocation) ----------------
__device__ float g_xlin[N_NODES * OUT_C];     // 12.8 MB, fits in L2
__device__ float g_ai[N_NODES], g_aj[N_NODES];
__device__ float g_is[N_NODES], g_js[N_NODES];  // combined tgt-side / src-side scalars
__device__ float g_sum[OUT_C], g_sumsq[OUT_C];
__device__ int   g_is64;

// ---------------- kernel 0: init + edge dtype detection ----------------
__global__ void k_init(const void* edge) {
    int t = threadIdx.x;
    if (t == 0) {
        // If edge_index is int64: every value < 50000 so the high 32-bit word of
        // each element is 0 -> words 1,3,5 are zero. If int32: words 1,3,5 are
        // src[1],src[3],src[5] which for tgt=0 are (0+off)%N with off in [1,N),
        // i.e. provably nonzero.
        const int* p = (const int*)edge;
        g_is64 = (p[1] == 0 && p[3] == 0 && p[5] == 0) ? 1 : 0;
    }
    if (t < OUT_C) { g_sum[t] = 0.0f; g_sumsq[t] = 0.0f; }
}

// ---------------- kernel 1: GEMM x@W^T + per-row attention scalar epilogue ----------------
// block: 256 threads, 64 rows per block. smem: xs[64][132], ws[64][132] (dynamic, ~67.6KB)
#define TM 64
#define PAD 132
__global__ void k_gemm(const float* __restrict__ x, const float* __restrict__ w,
                       const float* __restrict__ att_i, const float* __restrict__ att_j) {
    extern __shared__ float sm[];
    float* xs = sm;               // [64][PAD]
    float* ws = sm + TM * PAD;    // [64][PAD]
    int tid = threadIdx.x;
    int rowbase = blockIdx.x * TM;

    // load W (64x128) as float4
    const float4* w4 = (const float4*)w;
    for (int i = tid; i < OUT_C * (IN_C / 4); i += 256) {
        int r = i >> 5, k4 = i & 31;
        float4 v = w4[r * 32 + k4];
        float* d = &ws[r * PAD + k4 * 4];
        d[0] = v.x; d[1] = v.y; d[2] = v.z; d[3] = v.w;
    }
    // load x tile (64x128)
    const float4* x4 = (const float4*)x;
    for (int i = tid; i < TM * (IN_C / 4); i += 256) {
        int r = i >> 5, k4 = i & 31;
        int row = rowbase + r;
        float4 v = (row < N_NODES) ? x4[(long long)row * 32 + k4] : make_float4(0.f,0.f,0.f,0.f);
        float* d = &xs[r * PAD + k4 * 4];
        d[0] = v.x; d[1] = v.y; d[2] = v.z; d[3] = v.w;
    }
    __syncthreads();

    int r0 = tid >> 4;   // 0..15, rows {r0, r0+16, r0+32, r0+48}
    int c0 = tid & 15;   // 0..15, cols {c0, c0+16, c0+32, c0+48}
    float acc[4][4] = {};
    #pragma unroll 4
    for (int k = 0; k < IN_C; k++) {
        float xv[4], wv[4];
        #pragma unroll
        for (int i = 0; i < 4; i++) xv[i] = xs[(r0 + 16 * i) * PAD + k];
        #pragma unroll
        for (int j = 0; j < 4; j++) wv[j] = ws[(c0 + 16 * j) * PAD + k];
        #pragma unroll
        for (int i = 0; i < 4; i++)
            #pragma unroll
            for (int j = 0; j < 4; j++)
                acc[i][j] += xv[i] * wv[j];
    }

    // epilogue: store x_lin rows + reduce a_i, a_j per row across the 16 threads
    // sharing r0 (consecutive tids -> same half-warp)
    #pragma unroll
    for (int i = 0; i < 4; i++) {
        int row = rowbase + r0 + 16 * i;
        float pai = 0.f, paj = 0.f;
        if (row < N_NODES) {
            #pragma unroll
            for (int j = 0; j < 4; j++) {
                int c = c0 + 16 * j;
                g_xlin[(long long)row * OUT_C + c] = acc[i][j];
                pai += acc[i][j] * __ldg(&att_i[c]);
                paj += acc[i][j] * __ldg(&att_j[c]);
            }
        }
        #pragma unroll
        for (int off = 8; off > 0; off >>= 1) {
            pai += __shfl_down_sync(0xffffffffu, pai, off, 16);
            paj += __shfl_down_sync(0xffffffffu, paj, off, 16);
        }
        if (c0 == 0 && row < N_NODES) { g_ai[row] = pai; g_aj[row] = paj; }
    }
}

// ---------------- kernel 2: embedding scalars, fused with g_ai/g_aj into g_is/g_js ----------------
// one warp per node: lane reads channels {2l, 2l+1}
__global__ void k_emb(const float* __restrict__ emb,
                      const float* __restrict__ att_em_i,
                      const float* __restrict__ att_em_j) {
    int warp = (blockIdx.x * blockDim.x + threadIdx.x) >> 5;
    int lane = threadIdx.x & 31;
    if (warp >= N_NODES) return;
    float2 e = ((const float2*)emb)[(long long)warp * 32 + lane];
    float pei = e.x * __ldg(&att_em_i[2 * lane]) + e.y * __ldg(&att_em_i[2 * lane + 1]);
    float pej = e.x * __ldg(&att_em_j[2 * lane]) + e.y * __ldg(&att_em_j[2 * lane + 1]);
    #pragma unroll
    for (int off = 16; off > 0; off >>= 1) {
        pei += __shfl_xor_sync(0xffffffffu, pei, off);
        pej += __shfl_xor_sync(0xffffffffu, pej, off);
    }
    if (lane == 0) {
        g_is[warp] = g_ai[warp] + pei;   // tgt-side combined scalar
        g_js[warp] = g_aj[warp] + pej;   // src-side combined scalar
    }
}

// ---------------- kernel 3: attention softmax + weighted aggregation ----------------
// one warp per target node; 32 edges (lane each) + 1 self loop.
__global__ void k_aggr(const void* __restrict__ edge,
                       const float* __restrict__ bias,
                       float* __restrict__ out) {
    int warp = (blockIdx.x * blockDim.x + threadIdx.x) >> 5;
    int lane = threadIdx.x & 31;
    if (warp >= N_NODES) return;
    int v = warp;

    long long eidx = (long long)v * TOPK + lane;
    int src;
    if (g_is64) src = (int)((const long long*)edge)[eidx];
    else        src = ((const int*)edge)[eidx];

    float base = g_is[v];
    float al = base + g_js[src];
    al = (al >= 0.f) ? al : NEG_SLOPE * al;
    float aself = base + g_js[v];
    aself = (aself >= 0.f) ? aself : NEG_SLOPE * aself;

    // warp max over 33 values
    float m = al;
    #pragma unroll
    for (int off = 16; off > 0; off >>= 1)
        m = fmaxf(m, __shfl_xor_sync(0xffffffffu, m, off));
    m = fmaxf(m, aself);

    float ex = __expf(al - m);
    float s = ex;
    #pragma unroll
    for (int off = 16; off > 0; off >>= 1)
        s += __shfl_xor_sync(0xffffffffu, s, off);
    float exs = __expf(aself - m);
    float denom = s + exs + 1e-16f;
    float wgt = ex / denom;
    float wself = exs / denom;

    // aggregation: each lane owns channels {2l, 2l+1}; 256B coalesced row reads
    const float2* xl2 = (const float2*)g_xlin;
    float2 xself = xl2[(long long)v * 32 + lane];
    float ax = wself * xself.x, ay = wself * xself.y;
    #pragma unroll
    for (int i = 0; i < TOPK; i++) {
        float wi = __shfl_sync(0xffffffffu, wgt, i);
        int   si = __shfl_sync(0xffffffffu, src, i);
        float2 xv = xl2[(long long)si * 32 + lane];
        ax += wi * xv.x;
        ay += wi * xv.y;
    }
    ax += __ldg(&bias[2 * lane]);
    ay += __ldg(&bias[2 * lane + 1]);
    ((float2*)out)[(long long)v * 32 + lane] = make_float2(ax, ay);
}

// ---------------- kernel 4: BN batch stats (two-pass over d_out, L2-resident) ----------------
// 250 blocks x 256 threads; block handles 200 rows; thread = (rowgroup, channel)
__global__ void k_stats(const float* __restrict__ out) {
    int b = blockIdx.x, tid = threadIdx.x;
    int rstart = b * 200;
    int rend = rstart + 200; if (rend > N_NODES) rend = N_NODES;
    int c = tid & 63, rg = tid >> 6;
    float s = 0.f, q = 0.f;
    for (int r = rstart + rg; r < rend; r += 4) {
        float v = out[(long long)r * OUT_C + c];
        s += v; q += v * v;
    }
    __shared__ float ss[256], sq[256];
    ss[tid] = s; sq[tid] = q;
    __syncthreads();
    if (tid < 64) {
        float S = ss[tid] + ss[tid + 64] + ss[tid + 128] + ss[tid + 192];
        float Q = sq[tid] + sq[tid + 64] + sq[tid + 128] + sq[tid + 192];
        atomicAdd(&g_sum[tid], S);
        atomicAdd(&g_sumsq[tid], Q);
    }
}

// ---------------- kernel 5: normalize + affine + relu (in place on d_out) ----------------
__global__ void k_norm(float* __restrict__ out,
                       const float* __restrict__ gamma,
                       const float* __restrict__ beta) {
    const float invn = 1.0f / (float)N_NODES;
    int idx = blockIdx.x * blockDim.x + threadIdx.x;   // over N*32 float2
    if (idx >= N_NODES * 32) return;
    int c = (idx & 31) * 2;
    float2 v = ((float2*)out)[idx];
    float mu0 = g_sum[c] * invn;
    float mu1 = g_sum[c + 1] * invn;
    float var0 = g_sumsq[c] * invn - mu0 * mu0;
    float var1 = g_sumsq[c + 1] * invn - mu1 * mu1;
    float r0 = (v.x - mu0) * rsqrtf(var0 + BN_EPS) * __ldg(&gamma[c]) + __ldg(&beta[c]);
    float r1 = (v.y - mu1) * rsqrtf(var1 + BN_EPS) * __ldg(&gamma[c + 1]) + __ldg(&beta[c + 1]);
    ((float2*)out)[idx] = make_float2(fmaxf(r0, 0.f), fmaxf(r1, 0.f));
}

// ---------------- launch ----------------
extern "C" void kernel_launch(void* const* d_in, const int* in_sizes, int n_in,
                              void* d_out, int out_size) {
    const float* x        = (const float*)d_in[0];
    const float* emb      = (const float*)d_in[1];
    const void*  edge     = d_in[2];
    const float* lin_w    = (const float*)d_in[3];
    const float* att_i    = (const float*)d_in[4];
    const float* att_j    = (const float*)d_in[5];
    const float* att_em_i = (const float*)d_in[6];
    const float* att_em_j = (const float*)d_in[7];
    const float* bias     = (const float*)d_in[8];
    const float* bn_gamma = (const float*)d_in[9];
    const float* bn_beta  = (const float*)d_in[10];
    float* out = (float*)d_out;

    (void)in_sizes; (void)n_in; (void)out_size;

    k_init<<<1, 64>>>(edge);

    int smem = 2 * TM * PAD * sizeof(float);   // ~67.6 KB
    static bool attr_done = false;
    if (!attr_done) {
        cudaFuncSetAttribute(k_gemm, cudaFuncAttributeMaxDynamicSharedMemorySize, smem);
        attr_done = true;
    }
    int gemm_blocks = (N_NODES + TM - 1) / TM;  // 782
    k_gemm<<<gemm_blocks, 256, smem>>>(x, lin_w, att_i, att_j);

    k_emb<<<(N_NODES * 32 + 255) / 256, 256>>>(emb, att_em_i, att_em_j);

    k_aggr<<<(N_NODES * 32 + 255) / 256, 256>>>(edge, bias, out);

    k_stats<<<250, 256>>>(out);

    k_norm<<<(N_NODES * 32 + 255) / 256, 256>>>(out, bn_gamma, bn_beta);
}

// round 10
// speedup vs baseline: 1.3347x; 1.3347x over previous
#include <cuda_runtime.h>
#include <cuda_fp16.h>
#include <cstdint>

#define N_NODES 50000
#define TOPK    32
#define IN_C    128
#define OUT_C   64
#define NEG_SLOPE 0.2f
#define BN_EPS  1e-5f

// ---------------- scratch (static device globals; no allocation) ----------------
__device__ __align__(16) __half g_xlin[N_NODES * OUT_C];   // 6.4 MB, L2-resident
__device__ float g_ai[N_NODES], g_aj[N_NODES];
__device__ float g_is[N_NODES], g_js[N_NODES];
__device__ float g_sum[OUT_C], g_sumsq[OUT_C];
__device__ int   g_is64;

// ---------------- helpers ----------------
__device__ __forceinline__ uint32_t smem_u32(const void* p) {
    uint32_t a;
    asm("{ .reg .u64 t; cvta.to.shared.u64 t, %1; cvt.u32.u64 %0, t; }" : "=r"(a) : "l"(p));
    return a;
}
__device__ __forceinline__ void ldsm4(uint32_t* r, uint32_t addr) {
    asm volatile("ldmatrix.sync.aligned.m8n8.x4.shared.b16 {%0,%1,%2,%3}, [%4];"
        : "=r"(r[0]), "=r"(r[1]), "=r"(r[2]), "=r"(r[3]) : "r"(addr));
}
__device__ __forceinline__ void mma16816(float* c, const uint32_t* a, uint32_t b0, uint32_t b1) {
    asm volatile("mma.sync.aligned.m16n8k16.row.col.f32.f16.f16.f32 "
        "{%0,%1,%2,%3}, {%4,%5,%6,%7}, {%8,%9}, {%0,%1,%2,%3};"
        : "+f"(c[0]), "+f"(c[1]), "+f"(c[2]), "+f"(c[3])
        : "r"(a[0]), "r"(a[1]), "r"(a[2]), "r"(a[3]), "r"(b0), "r"(b1));
}
__device__ __forceinline__ uint32_t pack_hi(float a, float b) {
    __half2 h = __floats2half2_rn(a, b);
    return *reinterpret_cast<uint32_t*>(&h);
}
__device__ __forceinline__ uint32_t pack_lo(float a, float b, uint32_t hi) {
    __half2 h = *reinterpret_cast<__half2*>(&hi);
    float2 f = __half22float2(h);
    __half2 l = __floats2half2_rn(a - f.x, b - f.y);
    return *reinterpret_cast<uint32_t*>(&l);
}

// ---------------- kernel 0: init + edge dtype detection ----------------
__global__ void k_init(const void* edge) {
    int t = threadIdx.x;
    if (t == 0) {
        // int64 edges: high words of small values are 0 at odd word idx;
        // int32 edges: words 1,3,5 are src[1],src[3],src[5], provably nonzero.
        const int* p = (const int*)edge;
        g_is64 = (p[1] == 0 && p[3] == 0 && p[5] == 0) ? 1 : 0;
    }
    if (t < OUT_C) { g_sum[t] = 0.0f; g_sumsq[t] = 0.0f; }
}

// ---------------- kernel 1: HMMA GEMM (hi/lo fp16 split) + attention epilogue ----------------
// tile: 128 rows x 64 cols, K=128. 256 threads (8 warps, 16 rows each).
// smem halves, padded stride 136 (272B -> ldmatrix rows land on distinct banks).
#define ASTRIDE 136
#define OFF_AHI 0
#define OFF_ALO (128 * ASTRIDE * 2)
#define OFF_WHI (OFF_ALO + 128 * ASTRIDE * 2)
#define OFF_WLO (OFF_WHI + 64 * ASTRIDE * 2)
#define SM_TOTAL (OFF_WLO + 64 * ASTRIDE * 2)   // 104448 B

__global__ void __launch_bounds__(256, 2) k_gemm(const float* __restrict__ x,
                                                 const float* __restrict__ w,
                                                 const float* __restrict__ att_i,
                                                 const float* __restrict__ att_j) {
    extern __shared__ char sm[];
    uint32_t sb = smem_u32(sm);
    int tid = threadIdx.x, wid = tid >> 5, lane = tid & 31;
    int rowbase = blockIdx.x * 128;

    // load A tile: 128 rows x 128 k (fp32 -> hi/lo fp16)
    const float4* x4 = (const float4*)x;
    for (int i = tid; i < 128 * 32; i += 256) {
        int r = i >> 5, k4 = i & 31;
        int row = rowbase + r;
        float4 v = (row < N_NODES) ? x4[(size_t)row * 32 + k4] : make_float4(0.f, 0.f, 0.f, 0.f);
        uint32_t h0 = pack_hi(v.x, v.y), h1 = pack_hi(v.z, v.w);
        uint32_t l0 = pack_lo(v.x, v.y, h0), l1 = pack_lo(v.z, v.w, h1);
        uint32_t off = (uint32_t)(r * ASTRIDE + k4 * 4) * 2;
        *(uint2*)(sm + OFF_AHI + off) = make_uint2(h0, h1);
        *(uint2*)(sm + OFF_ALO + off) = make_uint2(l0, l1);
    }
    // load W tile: [64, 128] K-major (k contiguous => column-major B for row.col mma)
    const float4* w4 = (const float4*)w;
    for (int i = tid; i < 64 * 32; i += 256) {
        int r = i >> 5, k4 = i & 31;
        float4 v = w4[r * 32 + k4];
        uint32_t h0 = pack_hi(v.x, v.y), h1 = pack_hi(v.z, v.w);
        uint32_t l0 = pack_lo(v.x, v.y, h0), l1 = pack_lo(v.z, v.w, h1);
        uint32_t off = (uint32_t)(r * ASTRIDE + k4 * 4) * 2;
        *(uint2*)(sm + OFF_WHI + off) = make_uint2(h0, h1);
        *(uint2*)(sm + OFF_WLO + off) = make_uint2(l0, l1);
    }
    __syncthreads();

    int wr = wid * 16;               // warp's row base within tile
    int i8 = lane & 7, g = lane >> 3;

    // A frag addr: m = wr + (g&1)*8 + i8, k = kc*16 + (g>>1)*8
    uint32_t aoff = (uint32_t)((wr + (g & 1) * 8 + i8) * ASTRIDE + (g >> 1) * 8) * 2;
    // B frag addr (non-trans; [n][k] storage IS col-major B):
    //   matrix0: n 0-7 / k 0-7, matrix1: n 0-7 / k 8-15, matrix2/3: n 8-15
    uint32_t boff = (uint32_t)(((g >> 1) * 8 + i8) * ASTRIDE + (g & 1) * 8) * 2;

    float c[8][4];
    #pragma unroll
    for (int t = 0; t < 8; t++)
        #pragma unroll
        for (int j = 0; j < 4; j++) c[t][j] = 0.f;

    #pragma unroll
    for (int kc = 0; kc < 8; kc++) {
        uint32_t ah[4], al[4];
        ldsm4(ah, sb + OFF_AHI + aoff + kc * 32);
        ldsm4(al, sb + OFF_ALO + aoff + kc * 32);
        #pragma unroll
        for (int np = 0; np < 4; np++) {
            uint32_t bh[4], bl[4];
            uint32_t bo = boff + (uint32_t)(np * 16 * ASTRIDE) * 2 + kc * 32;
            ldsm4(bh, sb + OFF_WHI + bo);
            ldsm4(bl, sb + OFF_WLO + bo);
            mma16816(c[2 * np],     ah, bh[0], bh[1]);
            mma16816(c[2 * np + 1], ah, bh[2], bh[3]);
            mma16816(c[2 * np],     al, bh[0], bh[1]);
            mma16816(c[2 * np + 1], al, bh[2], bh[3]);
            mma16816(c[2 * np],     ah, bl[0], bl[1]);
            mma16816(c[2 * np + 1], ah, bl[2], bl[3]);
        }
    }

    // epilogue: thread owns rows {r0, r0+8}, cols {t*8 + q*2, +1} for t=0..7
    int q = lane & 3;
    int grow0 = rowbase + wr + (lane >> 2);
    int grow1 = grow0 + 8;
    float ai0 = 0.f, aj0 = 0.f, ai1 = 0.f, aj1 = 0.f;
    #pragma unroll
    for (int t = 0; t < 8; t++) {
        int col = t * 8 + q * 2;
        float w0 = __ldg(&att_i[col]), w1 = __ldg(&att_i[col + 1]);
        float u0 = __ldg(&att_j[col]), u1 = __ldg(&att_j[col + 1]);
        ai0 += c[t][0] * w0 + c[t][1] * w1;
        aj0 += c[t][0] * u0 + c[t][1] * u1;
        ai1 += c[t][2] * w0 + c[t][3] * w1;
        aj1 += c[t][2] * u0 + c[t][3] * u1;
        if (grow0 < N_NODES)
            *(uint32_t*)&g_xlin[(size_t)grow0 * OUT_C + col] = pack_hi(c[t][0], c[t][1]);
        if (grow1 < N_NODES)
            *(uint32_t*)&g_xlin[(size_t)grow1 * OUT_C + col] = pack_hi(c[t][2], c[t][3]);
    }
    // reduce the 4 col-pair lanes (quad) for per-row dots
    #pragma unroll
    for (int off = 2; off > 0; off >>= 1) {
        ai0 += __shfl_xor_sync(0xffffffffu, ai0, off);
        aj0 += __shfl_xor_sync(0xffffffffu, aj0, off);
        ai1 += __shfl_xor_sync(0xffffffffu, ai1, off);
        aj1 += __shfl_xor_sync(0xffffffffu, aj1, off);
    }
    if (q == 0) {
        if (grow0 < N_NODES) { g_ai[grow0] = ai0; g_aj[grow0] = aj0; }
        if (grow1 < N_NODES) { g_ai[grow1] = ai1; g_aj[grow1] = aj1; }
    }
}

// ---------------- kernel 2: embedding scalars, fused into g_is/g_js ----------------
__global__ void k_emb(const float* __restrict__ emb,
                      const float* __restrict__ att_em_i,
                      const float* __restrict__ att_em_j) {
    int warp = (blockIdx.x * blockDim.x + threadIdx.x) >> 5;
    int lane = threadIdx.x & 31;
    if (warp >= N_NODES) return;
    float2 e = ((const float2*)emb)[(size_t)warp * 32 + lane];
    float pei = e.x * __ldg(&att_em_i[2 * lane]) + e.y * __ldg(&att_em_i[2 * lane + 1]);
    float pej = e.x * __ldg(&att_em_j[2 * lane]) + e.y * __ldg(&att_em_j[2 * lane + 1]);
    #pragma unroll
    for (int off = 16; off > 0; off >>= 1) {
        pei += __shfl_xor_sync(0xffffffffu, pei, off);
        pej += __shfl_xor_sync(0xffffffffu, pej, off);
    }
    if (lane == 0) {
        g_is[warp] = g_ai[warp] + pei;
        g_js[warp] = g_aj[warp] + pej;
    }
}

// ---------------- kernel 3: softmax + weighted aggregation (fp16 gathers) ----------------
__global__ void k_aggr(const void* __restrict__ edge,
                       const float* __restrict__ bias,
                       float* __restrict__ out) {
    int warp = (blockIdx.x * blockDim.x + threadIdx.x) >> 5;
    int lane = threadIdx.x & 31;
    if (warp >= N_NODES) return;
    int v = warp;

    long long eidx = (long long)v * TOPK + lane;
    int src;
    if (g_is64) src = (int)((const long long*)edge)[eidx];
    else        src = ((const int*)edge)[eidx];

    float base = g_is[v];
    float al = base + g_js[src];
    al = (al >= 0.f) ? al : NEG_SLOPE * al;
    float aself = base + g_js[v];
    aself = (aself >= 0.f) ? aself : NEG_SLOPE * aself;

    float m = al;
    #pragma unroll
    for (int off = 16; off > 0; off >>= 1)
        m = fmaxf(m, __shfl_xor_sync(0xffffffffu, m, off));
    m = fmaxf(m, aself);

    float ex = __expf(al - m);
    float s = ex;
    #pragma unroll
    for (int off = 16; off > 0; off >>= 1)
        s += __shfl_xor_sync(0xffffffffu, s, off);
    float exs = __expf(aself - m);
    float denom = s + exs + 1e-16f;
    float wgt = ex / denom;
    float wself = exs / denom;

    // gathers: lane owns channels {2l, 2l+1}; fp16 rows are 128B -> 4 sectors/row
    const __half2* xl2 = (const __half2*)g_xlin;
    float2 xself = __half22float2(xl2[(size_t)v * 32 + lane]);
    float ax = wself * xself.x, ay = wself * xself.y;
    #pragma unroll
    for (int i = 0; i < TOPK; i++) {
        float wi = __shfl_sync(0xffffffffu, wgt, i);
        int   si = __shfl_sync(0xffffffffu, src, i);
        float2 xv = __half22float2(xl2[(size_t)si * 32 + lane]);
        ax += wi * xv.x;
        ay += wi * xv.y;
    }
    ax += __ldg(&bias[2 * lane]);
    ay += __ldg(&bias[2 * lane + 1]);
    ((float2*)out)[(size_t)v * 32 + lane] = make_float2(ax, ay);
}

// ---------------- kernel 4: BN batch stats ----------------
__global__ void k_stats(const float* __restrict__ out) {
    int b = blockIdx.x, tid = threadIdx.x;
    int rstart = b * 200;
    int rend = rstart + 200; if (rend > N_NODES) rend = N_NODES;
    int c = tid & 63, rg = tid >> 6;
    float s = 0.f, q = 0.f;
    for (int r = rstart + rg; r < rend; r += 4) {
        float v = out[(size_t)r * OUT_C + c];
        s += v; q += v * v;
    }
    __shared__ float ss[256], sq[256];
    ss[tid] = s; sq[tid] = q;
    __syncthreads();
    if (tid < 64) {
        float S = ss[tid] + ss[tid + 64] + ss[tid + 128] + ss[tid + 192];
        float Q = sq[tid] + sq[tid + 64] + sq[tid + 128] + sq[tid + 192];
        atomicAdd(&g_sum[tid], S);
        atomicAdd(&g_sumsq[tid], Q);
    }
}

// ---------------- kernel 5: normalize + affine + relu ----------------
__global__ void k_norm(float* __restrict__ out,
                       const float* __restrict__ gamma,
                       const float* __restrict__ beta) {
    const float invn = 1.0f / (float)N_NODES;
    int idx = blockIdx.x * blockDim.x + threadIdx.x;
    if (idx >= N_NODES * 32) return;
    int c = (idx & 31) * 2;
    float2 v = ((float2*)out)[idx];
    float mu0 = g_sum[c] * invn;
    float mu1 = g_sum[c + 1] * invn;
    float var0 = g_sumsq[c] * invn - mu0 * mu0;
    float var1 = g_sumsq[c + 1] * invn - mu1 * mu1;
    float r0 = (v.x - mu0) * rsqrtf(var0 + BN_EPS) * __ldg(&gamma[c]) + __ldg(&beta[c]);
    float r1 = (v.y - mu1) * rsqrtf(var1 + BN_EPS) * __ldg(&gamma[c + 1]) + __ldg(&beta[c + 1]);
    ((float2*)out)[idx] = make_float2(fmaxf(r0, 0.f), fmaxf(r1, 0.f));
}

// ---------------- launch ----------------
extern "C" void kernel_launch(void* const* d_in, const int* in_sizes, int n_in,
                              void* d_out, int out_size) {
    const float* x        = (const float*)d_in[0];
    const float* emb      = (const float*)d_in[1];
    const void*  edge     = d_in[2];
    const float* lin_w    = (const float*)d_in[3];
    const float* att_i    = (const float*)d_in[4];
    const float* att_j    = (const float*)d_in[5];
    const float* att_em_i = (const float*)d_in[6];
    const float* att_em_j = (const float*)d_in[7];
    const float* bias     = (const float*)d_in[8];
    const float* bn_gamma = (const float*)d_in[9];
    const float* bn_beta  = (const float*)d_in[10];
    float* out = (float*)d_out;

    (void)in_sizes; (void)n_in; (void)out_size;

    k_init<<<1, 64>>>(edge);

    static bool attr_done = false;
    if (!attr_done) {
        cudaFuncSetAttribute(k_gemm, cudaFuncAttributeMaxDynamicSharedMemorySize, SM_TOTAL);
        attr_done = true;
    }
    int gemm_blocks = (N_NODES + 127) / 128;   // 391
    k_gemm<<<gemm_blocks, 256, SM_TOTAL>>>(x, lin_w, att_i, att_j);

    k_emb<<<(N_NODES * 32 + 255) / 256, 256>>>(emb, att_em_i, att_em_j);

    k_aggr<<<(N_NODES * 32 + 255) / 256, 256>>>(edge, bias, out);

    k_stats<<<250, 256>>>(out);

    k_norm<<<(N_NODES * 32 + 255) / 256, 256>>>(out, bn_gamma, bn_beta);
}

// round 14
// speedup vs baseline: 1.4295x; 1.0710x over previous
#include <cuda_runtime.h>
#include <cuda_fp16.h>
#include <cstdint>

#define N_NODES 50000
#define TOPK    32
#define IN_C    128
#define OUT_C   64
#define NEG_SLOPE 0.2f
#define BN_EPS  1e-5f

// ---------------- scratch (static device globals; no allocation) ----------------
__device__ __align__(16) __half g_xlin[N_NODES * OUT_C];   // 6.4 MB, L2-resident
__device__ float g_is[N_NODES], g_js[N_NODES];
__device__ float g_sum[OUT_C], g_sumsq[OUT_C];
__device__ int   g_is64;

// ---------------- helpers ----------------
__device__ __forceinline__ uint32_t smem_u32(const void* p) {
    uint32_t a;
    asm("{ .reg .u64 t; cvta.to.shared.u64 t, %1; cvt.u32.u64 %0, t; }" : "=r"(a) : "l"(p));
    return a;
}
__device__ __forceinline__ void ldsm4(uint32_t* r, uint32_t addr) {
    asm volatile("ldmatrix.sync.aligned.m8n8.x4.shared.b16 {%0,%1,%2,%3}, [%4];"
        : "=r"(r[0]), "=r"(r[1]), "=r"(r[2]), "=r"(r[3]) : "r"(addr));
}
__device__ __forceinline__ void mma16816(float* c, const uint32_t* a, uint32_t b0, uint32_t b1) {
    asm volatile("mma.sync.aligned.m16n8k16.row.col.f32.f16.f16.f32 "
        "{%0,%1,%2,%3}, {%4,%5,%6,%7}, {%8,%9}, {%0,%1,%2,%3};"
        : "+f"(c[0]), "+f"(c[1]), "+f"(c[2]), "+f"(c[3])
        : "r"(a[0]), "r"(a[1]), "r"(a[2]), "r"(a[3]), "r"(b0), "r"(b1));
}
__device__ __forceinline__ uint32_t pack_hi(float a, float b) {
    __half2 h = __floats2half2_rn(a, b);
    return *reinterpret_cast<uint32_t*>(&h);
}

// ---------------- kernel 1: fp16 HMMA GEMM + emb dots + attention scalars ----------------
// tile: 128 rows x 64 cols, K=128. 256 threads (8 warps, 16 rows each).
// smem halves, padded stride 136 (272B rows -> conflict-free ldmatrix).
#define ASTRIDE 136
#define OFF_A 0
#define OFF_W (128 * ASTRIDE * 2)
#define SM_TOTAL (OFF_W + 64 * ASTRIDE * 2)   // 52224 B

__global__ void __launch_bounds__(256, 2) k_gemm(const float* __restrict__ x,
                                                 const float* __restrict__ w,
                                                 const float* __restrict__ att_i,
                                                 const float* __restrict__ att_j,
                                                 const float* __restrict__ emb,
                                                 const float* __restrict__ att_em_i,
                                                 const float* __restrict__ att_em_j,
                                                 const void*  __restrict__ edge) {
    extern __shared__ char sm[];
    uint32_t sb = smem_u32(sm);
    int tid = threadIdx.x, wid = tid >> 5, lane = tid & 31;
    int rowbase = blockIdx.x * 128;

    // fold k_init: edge dtype detection + BN-stat zeroing (block 0 only)
    if (blockIdx.x == 0) {
        if (tid == 0) {
            // int64 edges: odd 32-bit words of small values are 0;
            // int32 edges: words 1,3,5 = src[1],src[3],src[5], provably nonzero.
            const int* p = (const int*)edge;
            g_is64 = (p[1] == 0 && p[3] == 0 && p[5] == 0) ? 1 : 0;
        }
        if (tid < OUT_C) { g_sum[tid] = 0.0f; g_sumsq[tid] = 0.0f; }
    }

    // load A tile: 128 rows x 128 k (fp32 -> fp16)
    const float4* x4 = (const float4*)x;
    for (int i = tid; i < 128 * 32; i += 256) {
        int r = i >> 5, k4 = i & 31;
        int row = rowbase + r;
        float4 v = (row < N_NODES) ? x4[(size_t)row * 32 + k4] : make_float4(0.f, 0.f, 0.f, 0.f);
        uint32_t off = (uint32_t)(r * ASTRIDE + k4 * 4) * 2;
        *(uint2*)(sm + OFF_A + off) = make_uint2(pack_hi(v.x, v.y), pack_hi(v.z, v.w));
    }
    // load W tile: [64, 128] K-major (k contiguous => col-major B for row.col mma)
    const float4* w4 = (const float4*)w;
    for (int i = tid; i < 64 * 32; i += 256) {
        int r = i >> 5, k4 = i & 31;
        float4 v = w4[r * 32 + k4];
        uint32_t off = (uint32_t)(r * ASTRIDE + k4 * 4) * 2;
        *(uint2*)(sm + OFF_W + off) = make_uint2(pack_hi(v.x, v.y), pack_hi(v.z, v.w));
    }
    __syncthreads();

    int wr = wid * 16;               // warp's row base within tile
    int i8 = lane & 7, g = lane >> 3;

    // A frag: m = wr + (g&1)*8 + i8, k = kc*16 + (g>>1)*8
    uint32_t aoff = (uint32_t)((wr + (g & 1) * 8 + i8) * ASTRIDE + (g >> 1) * 8) * 2;
    // B frag (non-trans; [n][k] storage IS col-major B)
    uint32_t boff = (uint32_t)(((g >> 1) * 8 + i8) * ASTRIDE + (g & 1) * 8) * 2;

    float c[8][4];
    #pragma unroll
    for (int t = 0; t < 8; t++)
        #pragma unroll
        for (int j = 0; j < 4; j++) c[t][j] = 0.f;

    #pragma unroll
    for (int kc = 0; kc < 8; kc++) {
        uint32_t ah[4];
        ldsm4(ah, sb + OFF_A + aoff + kc * 32);
        #pragma unroll
        for (int np = 0; np < 4; np++) {
            uint32_t bh[4];
            ldsm4(bh, sb + OFF_W + boff + (uint32_t)(np * 16 * ASTRIDE) * 2 + kc * 32);
            mma16816(c[2 * np],     ah, bh[0], bh[1]);
            mma16816(c[2 * np + 1], ah, bh[2], bh[3]);
        }
    }

    // ---- epilogue: store fp16 x_lin rows + per-row att dots ----
    // thread owns rows {grow0, grow0+8}, cols {t*8 + q*2, +1}
    int q = lane & 3;
    int grow0 = rowbase + wr + (lane >> 2);
    int grow1 = grow0 + 8;
    float ai0 = 0.f, aj0 = 0.f, ai1 = 0.f, aj1 = 0.f;
    #pragma unroll
    for (int t = 0; t < 8; t++) {
        int col = t * 8 + q * 2;
        float w0 = __ldg(&att_i[col]), w1 = __ldg(&att_i[col + 1]);
        float u0 = __ldg(&att_j[col]), u1 = __ldg(&att_j[col + 1]);
        ai0 += c[t][0] * w0 + c[t][1] * w1;
        aj0 += c[t][0] * u0 + c[t][1] * u1;
        ai1 += c[t][2] * w0 + c[t][3] * w1;
        aj1 += c[t][2] * u0 + c[t][3] * u1;
        if (grow0 < N_NODES)
            *(uint32_t*)&g_xlin[(size_t)grow0 * OUT_C + col] = pack_hi(c[t][0], c[t][1]);
        if (grow1 < N_NODES)
            *(uint32_t*)&g_xlin[(size_t)grow1 * OUT_C + col] = pack_hi(c[t][2], c[t][3]);
    }
    #pragma unroll
    for (int off = 2; off > 0; off >>= 1) {
        ai0 += __shfl_xor_sync(0xffffffffu, ai0, off);
        aj0 += __shfl_xor_sync(0xffffffffu, aj0, off);
        ai1 += __shfl_xor_sync(0xffffffffu, ai1, off);
        aj1 += __shfl_xor_sync(0xffffffffu, aj1, off);
    }

    // ---- fused k_emb: per-row emb dots; lane q covers channels q*16..q*16+15 ----
    float4 emi[4], emj[4];
    #pragma unroll
    for (int t = 0; t < 4; t++) {
        emi[t] = __ldg((const float4*)att_em_i + q * 4 + t);
        emj[t] = __ldg((const float4*)att_em_j + q * 4 + t);
    }
    #pragma unroll
    for (int p = 0; p < 2; p++) {
        int row = rowbase + wr + p * 8 + (lane >> 2);
        float pei = 0.f, pej = 0.f;
        if (row < N_NODES) {
            const float4* er = (const float4*)(emb + (size_t)row * OUT_C) + q * 4;
            #pragma unroll
            for (int t = 0; t < 4; t++) {
                float4 v = __ldg(er + t);
                pei += v.x * emi[t].x + v.y * emi[t].y + v.z * emi[t].z + v.w * emi[t].w;
                pej += v.x * emj[t].x + v.y * emj[t].y + v.z * emj[t].z + v.w * emj[t].w;
            }
        }
        #pragma unroll
        for (int off = 2; off > 0; off >>= 1) {
            pei += __shfl_xor_sync(0xffffffffu, pei, off);
            pej += __shfl_xor_sync(0xffffffffu, pej, off);
        }
        if (q == 0 && row < N_NODES) {
            if (p == 0) { g_is[row] = ai0 + pei; g_js[row] = aj0 + pej; }
            else        { g_is[row] = ai1 + pei; g_js[row] = aj1 + pej; }
        }
    }
}

// ---------------- kernel 2: softmax + aggregation + fused BN stats ----------------
__global__ void __launch_bounds__(256) k_aggr(const void* __restrict__ edge,
                                              const float* __restrict__ bias,
                                              float* __restrict__ out) {
    __shared__ uint2 ws[8][32];
    __shared__ float bsum[OUT_C], bsq[OUT_C];
    int tid = threadIdx.x, wid = tid >> 5, lane = tid & 31;
    if (tid < OUT_C) { bsum[tid] = 0.f; bsq[tid] = 0.f; }
    __syncthreads();

    int v = blockIdx.x * 8 + wid;    // grid 6250 * 8 warps = exactly 50000

    long long eidx = (long long)v * TOPK + lane;
    int src;
    if (g_is64) src = (int)((const long long*)edge)[eidx];
    else        src = ((const int*)edge)[eidx];

    float base = g_is[v];
    float al = base + g_js[src];
    al = (al >= 0.f) ? al : NEG_SLOPE * al;
    float aself = base + g_js[v];
    aself = (aself >= 0.f) ? aself : NEG_SLOPE * aself;

    float m = al;
    #pragma unroll
    for (int off = 16; off > 0; off >>= 1)
        m = fmaxf(m, __shfl_xor_sync(0xffffffffu, m, off));
    m = fmaxf(m, aself);

    float ex = __expf(al - m);
    float s = ex;
    #pragma unroll
    for (int off = 16; off > 0; off >>= 1)
        s += __shfl_xor_sync(0xffffffffu, s, off);
    float exs = __expf(aself - m);
    float denom = s + exs + 1e-16f;
    float wgt = ex / denom;
    float wself = exs / denom;

    // stage (weight, src) pairs; inner loop reads via LDS.64 broadcast (no shfl)
    ws[wid][lane] = make_uint2(__float_as_uint(wgt), (uint32_t)src);
    __syncwarp();

    const __half2* xl2 = (const __half2*)g_xlin;
    float2 xself = __half22float2(xl2[(uint32_t)v * 32 + lane]);
    float ax = wself * xself.x, ay = wself * xself.y;
    #pragma unroll
    for (int i = 0; i < TOPK; i++) {
        uint2 p = ws[wid][i];
        float wi = __uint_as_float(p.x);
        float2 xv = __half22float2(xl2[p.y * 32 + lane]);
        ax += wi * xv.x;
        ay += wi * xv.y;
    }
    ax += __ldg(&bias[2 * lane]);
    ay += __ldg(&bias[2 * lane + 1]);
    ((float2*)out)[(uint32_t)v * 32 + lane] = make_float2(ax, ay);

    // fused BN stats: block-level smem accumulation, then 128 global atomics
    atomicAdd(&bsum[2 * lane], ax);
    atomicAdd(&bsum[2 * lane + 1], ay);
    atomicAdd(&bsq[2 * lane], ax * ax);
    atomicAdd(&bsq[2 * lane + 1], ay * ay);
    __syncthreads();
    if (tid < OUT_C)            atomicAdd(&g_sum[tid], bsum[tid]);
    else if (tid < 2 * OUT_C)   atomicAdd(&g_sumsq[tid - OUT_C], bsq[tid - OUT_C]);
}

// ---------------- kernel 3: normalize + affine + relu ----------------
__global__ void k_norm(float* __restrict__ out,
                       const float* __restrict__ gamma,
                       const float* __restrict__ beta) {
    const float invn = 1.0f / (float)N_NODES;
    int idx = blockIdx.x * blockDim.x + threadIdx.x;
    if (idx >= N_NODES * 32) return;
    int c = (idx & 31) * 2;
    float2 v = ((float2*)out)[idx];
    float mu0 = g_sum[c] * invn;
    float mu1 = g_sum[c + 1] * invn;
    float var0 = g_sumsq[c] * invn - mu0 * mu0;
    float var1 = g_sumsq[c + 1] * invn - mu1 * mu1;
    float r0 = (v.x - mu0) * rsqrtf(var0 + BN_EPS) * __ldg(&gamma[c]) + __ldg(&beta[c]);
    float r1 = (v.y - mu1) * rsqrtf(var1 + BN_EPS) * __ldg(&gamma[c + 1]) + __ldg(&beta[c + 1]);
    ((float2*)out)[idx] = make_float2(fmaxf(r0, 0.f), fmaxf(r1, 0.f));
}

// ---------------- launch ----------------
extern "C" void kernel_launch(void* const* d_in, const int* in_sizes, int n_in,
                              void* d_out, int out_size) {
    const float* x        = (const float*)d_in[0];
    const float* emb      = (const float*)d_in[1];
    const void*  edge     = d_in[2];
    const float* lin_w    = (const float*)d_in[3];
    const float* att_i    = (const float*)d_in[4];
    const float* att_j    = (const float*)d_in[5];
    const float* att_em_i = (const float*)d_in[6];
    const float* att_em_j = (const float*)d_in[7];
    const float* bias     = (const float*)d_in[8];
    const float* bn_gamma = (const float*)d_in[9];
    const float* bn_beta  = (const float*)d_in[10];
    float* out = (float*)d_out;

    (void)in_sizes; (void)n_in; (void)out_size;

    static bool attr_done = false;
    if (!attr_done) {
        cudaFuncSetAttribute(k_gemm, cudaFuncAttributeMaxDynamicSharedMemorySize, SM_TOTAL);
        attr_done = true;
    }
    int gemm_blocks = (N_NODES + 127) / 128;   // 391
    k_gemm<<<gemm_blocks, 256, SM_TOTAL>>>(x, lin_w, att_i, att_j,
                                           emb, att_em_i, att_em_j, edge);

    k_aggr<<<N_NODES / 8, 256>>>(edge, bias, out);   // 6250 blocks

    k_norm<<<(N_NODES * 32 + 255) / 256, 256>>>(out, bn_gamma, bn_beta);
}

// round 17
// speedup vs baseline: 1.5790x; 1.1046x over previous
#include <cuda_runtime.h>
#include <cuda_fp16.h>
#include <cstdint>

#define N_NODES 50000
#define TOPK    32
#define IN_C    128
#define OUT_C   64
#define NEG_SLOPE 0.2f
#define BN_EPS  1e-5f

// ---------------- scratch (static device globals; no allocation) ----------------
__device__ __align__(16) __half g_xlin[N_NODES * OUT_C];   // 6.4 MB, L2-resident
__device__ float g_is[N_NODES], g_js[N_NODES];
__device__ float g_sum[OUT_C], g_sumsq[OUT_C];
__device__ int   g_is64;

// ---------------- helpers ----------------
__device__ __forceinline__ uint32_t smem_u32(const void* p) {
    uint32_t a;
    asm("{ .reg .u64 t; cvta.to.shared.u64 t, %1; cvt.u32.u64 %0, t; }" : "=r"(a) : "l"(p));
    return a;
}
__device__ __forceinline__ void ldsm4(uint32_t* r, uint32_t addr) {
    asm volatile("ldmatrix.sync.aligned.m8n8.x4.shared.b16 {%0,%1,%2,%3}, [%4];"
        : "=r"(r[0]), "=r"(r[1]), "=r"(r[2]), "=r"(r[3]) : "r"(addr));
}
__device__ __forceinline__ void mma16816(float* c, const uint32_t* a, uint32_t b0, uint32_t b1) {
    asm volatile("mma.sync.aligned.m16n8k16.row.col.f32.f16.f16.f32 "
        "{%0,%1,%2,%3}, {%4,%5,%6,%7}, {%8,%9}, {%0,%1,%2,%3};"
        : "+f"(c[0]), "+f"(c[1]), "+f"(c[2]), "+f"(c[3])
        : "r"(a[0]), "r"(a[1]), "r"(a[2]), "r"(a[3]), "r"(b0), "r"(b1));
}
__device__ __forceinline__ uint32_t pack_hi(float a, float b) {
    __half2 h = __floats2half2_rn(a, b);
    return *reinterpret_cast<uint32_t*>(&h);
}

// ---------------- kernel 1: fp16 HMMA GEMM + emb dots + attention scalars ----------------
// tile: 64 rows x 64 cols, K=128. 256 threads (8 warps).
// warp w: rows (w&3)*16, col-half (w>>2)*32  -> 16 accum regs/thread.
#define ASTRIDE 136
#define OFF_A 0
#define OFF_W (64 * ASTRIDE * 2)
#define SM_TOTAL (OFF_W + 64 * ASTRIDE * 2)   // 34816 B

__global__ void __launch_bounds__(256, 4) k_gemm(const float* __restrict__ x,
                                                 const float* __restrict__ w,
                                                 const float* __restrict__ att_i,
                                                 const float* __restrict__ att_j,
                                                 const float* __restrict__ emb,
                                                 const float* __restrict__ att_em_i,
                                                 const float* __restrict__ att_em_j,
                                                 const void*  __restrict__ edge) {
    extern __shared__ char sm[];
    __shared__ float sAI[64], sAJ[64];
    uint32_t sb = smem_u32(sm);
    int tid = threadIdx.x, wid = tid >> 5, lane = tid & 31;
    int rowbase = blockIdx.x * 64;

    // fold k_init (block 0 only)
    if (blockIdx.x == 0) {
        if (tid == 0) {
            // int64 edges: odd 32-bit words of small values are 0;
            // int32 edges: words 1,3,5 = src[1],src[3],src[5], provably nonzero.
            const int* p = (const int*)edge;
            g_is64 = (p[1] == 0 && p[3] == 0 && p[5] == 0) ? 1 : 0;
        }
        if (tid < OUT_C) { g_sum[tid] = 0.0f; g_sumsq[tid] = 0.0f; }
    }

    // load A tile: 64 rows x 128 k (fp32 -> fp16)
    const float4* x4 = (const float4*)x;
    #pragma unroll
    for (int i = tid; i < 64 * 32; i += 256) {
        int r = i >> 5, k4 = i & 31;
        int row = rowbase + r;
        float4 v = (row < N_NODES) ? x4[(size_t)row * 32 + k4] : make_float4(0.f, 0.f, 0.f, 0.f);
        uint32_t off = (uint32_t)(r * ASTRIDE + k4 * 4) * 2;
        *(uint2*)(sm + OFF_A + off) = make_uint2(pack_hi(v.x, v.y), pack_hi(v.z, v.w));
    }
    // load W: full [64, 128] K-major (k contiguous => col-major B for row.col mma)
    const float4* w4 = (const float4*)w;
    #pragma unroll
    for (int i = tid; i < 64 * 32; i += 256) {
        int r = i >> 5, k4 = i & 31;
        float4 v = w4[r * 32 + k4];
        uint32_t off = (uint32_t)(r * ASTRIDE + k4 * 4) * 2;
        *(uint2*)(sm + OFF_W + off) = make_uint2(pack_hi(v.x, v.y), pack_hi(v.z, v.w));
    }

    // ---- emb dots issued early (overlap DRAM latency with tile-load drain) ----
    // thread t: row tid>>2 in tile, qq = tid&3 covers channels qq*16..qq*16+15
    float pei = 0.f, pej = 0.f;
    {
        int rowt = tid >> 2, qq = tid & 3;
        int row = rowbase + rowt;
        if (row < N_NODES) {
            const float4* er = (const float4*)(emb + (size_t)row * OUT_C) + qq * 4;
            #pragma unroll
            for (int t = 0; t < 4; t++) {
                float4 v  = __ldg(er + t);
                float4 ei = __ldg((const float4*)att_em_i + qq * 4 + t);
                float4 ej = __ldg((const float4*)att_em_j + qq * 4 + t);
                pei += v.x * ei.x + v.y * ei.y + v.z * ei.z + v.w * ei.w;
                pej += v.x * ej.x + v.y * ej.y + v.z * ej.z + v.w * ej.w;
            }
        }
        #pragma unroll
        for (int off = 2; off > 0; off >>= 1) {
            pei += __shfl_xor_sync(0xffffffffu, pei, off);
            pej += __shfl_xor_sync(0xffffffffu, pej, off);
        }
    }
    __syncthreads();

    int rw = (wid & 3) * 16;         // warp row group
    int ch = wid >> 2;               // col half (0: cols 0-31, 1: cols 32-63)
    int i8 = lane & 7, g = lane >> 3;

    // A frag: m = rw + (g&1)*8 + i8, k = kc*16 + (g>>1)*8
    uint32_t aoff = (uint32_t)((rw + (g & 1) * 8 + i8) * ASTRIDE + (g >> 1) * 8) * 2;
    // B frag (non-trans; [n][k] storage IS col-major B): n = ch*32 + np*16 + (g>>1)*8 + i8
    uint32_t boff = (uint32_t)((ch * 32 + (g >> 1) * 8 + i8) * ASTRIDE + (g & 1) * 8) * 2;

    float c[4][4];
    #pragma unroll
    for (int t = 0; t < 4; t++)
        #pragma unroll
        for (int j = 0; j < 4; j++) c[t][j] = 0.f;

    #pragma unroll
    for (int kc = 0; kc < 8; kc++) {
        uint32_t ah[4];
        ldsm4(ah, sb + OFF_A + aoff + kc * 32);
        #pragma unroll
        for (int np = 0; np < 2; np++) {
            uint32_t bh[4];
            ldsm4(bh, sb + OFF_W + boff + (uint32_t)(np * 16 * ASTRIDE) * 2 + kc * 32);
            mma16816(c[2 * np],     ah, bh[0], bh[1]);
            mma16816(c[2 * np + 1], ah, bh[2], bh[3]);
        }
    }

    // ---- epilogue: store fp16 x_lin + att dots ----
    // thread owns rows {rt0, rt0+8} (tile-rel), cols {ch*32 + t*8 + q*2, +1}
    int q = lane & 3;
    int rt0 = rw + (lane >> 2);
    int grow0 = rowbase + rt0, grow1 = grow0 + 8;
    float ai0 = 0.f, aj0 = 0.f, ai1 = 0.f, aj1 = 0.f;
    #pragma unroll
    for (int t = 0; t < 4; t++) {
        int col = ch * 32 + t * 8 + q * 2;
        float w0 = __ldg(&att_i[col]), w1 = __ldg(&att_i[col + 1]);
        float u0 = __ldg(&att_j[col]), u1 = __ldg(&att_j[col + 1]);
        ai0 += c[t][0] * w0 + c[t][1] * w1;
        aj0 += c[t][0] * u0 + c[t][1] * u1;
        ai1 += c[t][2] * w0 + c[t][3] * w1;
        aj1 += c[t][2] * u0 + c[t][3] * u1;
        if (grow0 < N_NODES)
            *(uint32_t*)&g_xlin[(size_t)grow0 * OUT_C + col] = pack_hi(c[t][0], c[t][1]);
        if (grow1 < N_NODES)
            *(uint32_t*)&g_xlin[(size_t)grow1 * OUT_C + col] = pack_hi(c[t][2], c[t][3]);
    }
    #pragma unroll
    for (int off = 2; off > 0; off >>= 1) {
        ai0 += __shfl_xor_sync(0xffffffffu, ai0, off);
        aj0 += __shfl_xor_sync(0xffffffffu, aj0, off);
        ai1 += __shfl_xor_sync(0xffffffffu, ai1, off);
        aj1 += __shfl_xor_sync(0xffffffffu, aj1, off);
    }
    // cross-col-half combine via smem: ch=1 writes partials, ch=0 totals
    if (q == 0 && ch == 1) {
        sAI[rt0] = ai0; sAJ[rt0] = aj0;
        sAI[rt0 + 8] = ai1; sAJ[rt0 + 8] = aj1;
    }
    __syncthreads();
    if (q == 0 && ch == 0) {
        sAI[rt0] += ai0; sAJ[rt0] += aj0;
        sAI[rt0 + 8] += ai1; sAJ[rt0 + 8] += aj1;
    }
    __syncthreads();
    // final: thread qq==0 of each row-quad adds emb dot and writes globals
    {
        int rowt = tid >> 2, qq = tid & 3;
        int row = rowbase + rowt;
        if (qq == 0 && row < N_NODES) {
            g_is[row] = sAI[rowt] + pei;
            g_js[row] = sAJ[rowt] + pej;
        }
    }
}

// ---------------- kernel 2: softmax + aggregation + fused BN stats ----------------
__global__ void __launch_bounds__(256) k_aggr(const void* __restrict__ edge,
                                              const float* __restrict__ bias,
                                              float* __restrict__ out) {
    __shared__ uint2 ws[8][32];
    __shared__ float bsum[OUT_C], bsq[OUT_C];
    int tid = threadIdx.x, wid = tid >> 5, lane = tid & 31;
    if (tid < OUT_C) { bsum[tid] = 0.f; bsq[tid] = 0.f; }
    __syncthreads();

    int v = blockIdx.x * 8 + wid;    // grid 6250 * 8 warps = exactly 50000

    long long eidx = (long long)v * TOPK + lane;
    int src;
    if (g_is64) src = (int)((const long long*)edge)[eidx];
    else        src = ((const int*)edge)[eidx];

    float base = g_is[v];
    float al = base + g_js[src];
    al = (al >= 0.f) ? al : NEG_SLOPE * al;
    float aself = base + g_js[v];
    aself = (aself >= 0.f) ? aself : NEG_SLOPE * aself;

    float m = al;
    #pragma unroll
    for (int off = 16; off > 0; off >>= 1)
        m = fmaxf(m, __shfl_xor_sync(0xffffffffu, m, off));
    m = fmaxf(m, aself);

    float ex = __expf(al - m);
    float s = ex;
    #pragma unroll
    for (int off = 16; off > 0; off >>= 1)
        s += __shfl_xor_sync(0xffffffffu, s, off);
    float exs = __expf(aself - m);
    float denom = s + exs + 1e-16f;
    float wgt = ex / denom;
    float wself = exs / denom;

    // stage (weight, src) pairs; inner loop reads via LDS.64 broadcast (no shfl)
    ws[wid][lane] = make_uint2(__float_as_uint(wgt), (uint32_t)src);
    __syncwarp();

    const __half2* xl2 = (const __half2*)g_xlin;
    float2 xself = __half22float2(xl2[(uint32_t)v * 32 + lane]);
    float ax = wself * xself.x, ay = wself * xself.y;
    #pragma unroll
    for (int i = 0; i < TOPK; i++) {
        uint2 p = ws[wid][i];
        float wi = __uint_as_float(p.x);
        float2 xv = __half22float2(xl2[p.y * 32 + lane]);
        ax += wi * xv.x;
        ay += wi * xv.y;
    }
    ax += __ldg(&bias[2 * lane]);
    ay += __ldg(&bias[2 * lane + 1]);
    ((float2*)out)[(uint32_t)v * 32 + lane] = make_float2(ax, ay);

    // fused BN stats: block-level smem accumulation, then 128 global atomics
    atomicAdd(&bsum[2 * lane], ax);
    atomicAdd(&bsum[2 * lane + 1], ay);
    atomicAdd(&bsq[2 * lane], ax * ax);
    atomicAdd(&bsq[2 * lane + 1], ay * ay);
    __syncthreads();
    if (tid < OUT_C)            atomicAdd(&g_sum[tid], bsum[tid]);
    else if (tid < 2 * OUT_C)   atomicAdd(&g_sumsq[tid - OUT_C], bsq[tid - OUT_C]);
}

// ---------------- kernel 3: normalize + affine + relu ----------------
__global__ void k_norm(float* __restrict__ out,
                       const float* __restrict__ gamma,
                       const float* __restrict__ beta) {
    const float invn = 1.0f / (float)N_NODES;
    int idx = blockIdx.x * blockDim.x + threadIdx.x;
    if (idx >= N_NODES * 32) return;
    int c = (idx & 31) * 2;
    float2 v = ((float2*)out)[idx];
    float mu0 = g_sum[c] * invn;
    float mu1 = g_sum[c + 1] * invn;
    float var0 = g_sumsq[c] * invn - mu0 * mu0;
    float var1 = g_sumsq[c + 1] * invn - mu1 * mu1;
    float r0 = (v.x - mu0) * rsqrtf(var0 + BN_EPS) * __ldg(&gamma[c]) + __ldg(&beta[c]);
    float r1 = (v.y - mu1) * rsqrtf(var1 + BN_EPS) * __ldg(&gamma[c + 1]) + __ldg(&beta[c + 1]);
    ((float2*)out)[idx] = make_float2(fmaxf(r0, 0.f), fmaxf(r1, 0.f));
}

// ---------------- launch ----------------
extern "C" void kernel_launch(void* const* d_in, const int* in_sizes, int n_in,
                              void* d_out, int out_size) {
    const float* x        = (const float*)d_in[0];
    const float* emb      = (const float*)d_in[1];
    const void*  edge     = d_in[2];
    const float* lin_w    = (const float*)d_in[3];
    const float* att_i    = (const float*)d_in[4];
    const float* att_j    = (const float*)d_in[5];
    const float* att_em_i = (const float*)d_in[6];
    const float* att_em_j = (const float*)d_in[7];
    const float* bias     = (const float*)d_in[8];
    const float* bn_gamma = (const float*)d_in[9];
    const float* bn_beta  = (const float*)d_in[10];
    float* out = (float*)d_out;

    (void)in_sizes; (void)n_in; (void)out_size;

    static bool attr_done = false;
    if (!attr_done) {
        cudaFuncSetAttribute(k_gemm, cudaFuncAttributeMaxDynamicSharedMemorySize, SM_TOTAL);
        attr_done = true;
    }
    int gemm_blocks = (N_NODES + 63) / 64;   // 782
    k_gemm<<<gemm_blocks, 256, SM_TOTAL>>>(x, lin_w, att_i, att_j,
                                           emb, att_em_i, att_em_j, edge);

    k_aggr<<<N_NODES / 8, 256>>>(edge, bias, out);   // 6250 blocks

    k_norm<<<(N_NODES * 32 + 255) / 256, 256>>>(out, bn_gamma, bn_beta);
}